// round 1
// baseline (speedup 1.0000x reference)
#include <cuda_runtime.h>

#define NN 2048
#define HH 256
#define NJ 5
#define RSQ2 0.70710678118654752440f

// Static device scratch (allowed; no runtime allocation).
__device__ float g_Af[(size_t)NJ * NN * NN];   // 83.9 MB: cos-transformed A, 5 slices
__device__ float g_Xf[(size_t)NJ * NN * HH];   // 10.5 MB
__device__ float g_Wf[(size_t)NJ * HH * HH];   // 1.3 MB
__device__ float g_C1[(size_t)NJ * NN * HH];   // 10.5 MB
__device__ float g_C2[(size_t)NJ * NN * HH];   // 10.5 MB

// ---------------------------------------------------------------------------
// Forward cos transform along rel dim (8 -> 5 distinct frequencies).
// in:  [n][8] contiguous.  out: 5 slices of length sstride (slice j at j*sstride).
// f0 = sum;  f1/f3 = (x0-x4) +/- r*(x1-x3-x5+x7);  f2 = x0-x2+x4-x6;  f4 = alternating.
// ---------------------------------------------------------------------------
__global__ void fwd_transform_kernel(const float* __restrict__ in,
                                     float* __restrict__ out,
                                     int n, size_t sstride) {
    int i = blockIdx.x * blockDim.x + threadIdx.x;
    if (i >= n) return;
    const float4* p = reinterpret_cast<const float4*>(in) + (size_t)2 * i;
    float4 lo = p[0];   // x0..x3
    float4 hi = p[1];   // x4..x7

    float s04 = lo.x + hi.x, d04 = lo.x - hi.x;
    float s26 = lo.z + hi.z;
    float s15 = lo.y + hi.y, d15 = lo.y - hi.y;
    float s37 = lo.w + hi.w, d37 = lo.w - hi.w;

    float f0 = (s04 + s26) + (s15 + s37);
    float f2 = s04 - s26;
    float f4 = (s04 + s26) - (s15 + s37);
    float t  = RSQ2 * (d15 - d37);   // r*(x1 - x3 - x5 + x7)
    float f1 = d04 + t;
    float f3 = d04 - t;

    out[0 * sstride + i] = f0;
    out[1 * sstride + i] = f1;
    out[2 * sstride + i] = f2;
    out[3 * sstride + i] = f3;
    out[4 * sstride + i] = f4;
}

// ---------------------------------------------------------------------------
// Batched tiled SGEMM: C[z] = A[z] (MxK, ld=K) * B[z] (KxN, ld=N), z = blockIdx.z.
// BM=128, BN=64, BK=16, 256 threads, 8x4 per-thread micro-tile.
// Single-buffer smem with register prefetch of the next K-tile.
// M%BM == 0, N%BN == 0, K%BK == 0 guaranteed by problem shapes.
// ---------------------------------------------------------------------------
#define BM 128
#define BN 64
#define BK 16
#define TM 8
#define TN 4

__global__ __launch_bounds__(256, 3)
void sgemm_kernel(const float* __restrict__ A, const float* __restrict__ B,
                  float* __restrict__ C,
                  int M, int N, int K, size_t sA, size_t sB, size_t sC) {
    __shared__ float As[BK][BM + 4];   // [k][m], padded against bank conflicts
    __shared__ float Bs[BK][BN];       // [k][n]

    const float* Aj = A + (size_t)blockIdx.z * sA;
    const float* Bj = B + (size_t)blockIdx.z * sB;
    float*       Cj = C + (size_t)blockIdx.z * sC;

    const int tid  = threadIdx.x;
    const int m0   = blockIdx.y * BM;
    const int n0   = blockIdx.x * BN;
    const int trow = tid >> 4;          // 0..15 -> M rows trow*8..+7
    const int tcol = tid & 15;          // 0..15 -> N cols tcol*4..+3

    // Global->smem load mappings
    const int ar = tid >> 2;            // 0..63 (A rows ar and ar+64)
    const int ac = (tid & 3) << 2;      // 0,4,8,12 within BK
    const int br = tid >> 4;            // 0..15 (B row within BK)
    const int bc = (tid & 15) << 2;     // 0..60 within BN

    float acc[TM][TN];
#pragma unroll
    for (int i = 0; i < TM; i++)
#pragma unroll
        for (int j = 0; j < TN; j++) acc[i][j] = 0.0f;

    const int KT = K / BK;

    // Prologue: stage tile kt=0 into registers.
    float4 aR0 = *reinterpret_cast<const float4*>(&Aj[(size_t)(m0 + ar) * K + ac]);
    float4 aR1 = *reinterpret_cast<const float4*>(&Aj[(size_t)(m0 + ar + 64) * K + ac]);
    float4 bR  = *reinterpret_cast<const float4*>(&Bj[(size_t)br * N + n0 + bc]);

    for (int kt = 0; kt < KT; ++kt) {
        // Commit staged registers to smem (previous iteration's trailing sync
        // guarantees no one is still reading).
        As[ac + 0][ar]      = aR0.x;
        As[ac + 1][ar]      = aR0.y;
        As[ac + 2][ar]      = aR0.z;
        As[ac + 3][ar]      = aR0.w;
        As[ac + 0][ar + 64] = aR1.x;
        As[ac + 1][ar + 64] = aR1.y;
        As[ac + 2][ar + 64] = aR1.z;
        As[ac + 3][ar + 64] = aR1.w;
        *reinterpret_cast<float4*>(&Bs[br][bc]) = bR;
        __syncthreads();

        // Prefetch next K-tile into registers (hidden under the FMA block).
        if (kt + 1 < KT) {
            int kk = (kt + 1) * BK;
            aR0 = *reinterpret_cast<const float4*>(&Aj[(size_t)(m0 + ar) * K + kk + ac]);
            aR1 = *reinterpret_cast<const float4*>(&Aj[(size_t)(m0 + ar + 64) * K + kk + ac]);
            bR  = *reinterpret_cast<const float4*>(&Bj[(size_t)(kk + br) * N + n0 + bc]);
        }

#pragma unroll
        for (int k = 0; k < BK; k++) {
            float4 a0 = *reinterpret_cast<const float4*>(&As[k][trow * TM]);
            float4 a1 = *reinterpret_cast<const float4*>(&As[k][trow * TM + 4]);
            float4 b  = *reinterpret_cast<const float4*>(&Bs[k][tcol * TN]);
            float av[TM] = {a0.x, a0.y, a0.z, a0.w, a1.x, a1.y, a1.z, a1.w};
            float bv[TN] = {b.x, b.y, b.z, b.w};
#pragma unroll
            for (int i = 0; i < TM; i++)
#pragma unroll
                for (int j = 0; j < TN; j++) acc[i][j] += av[i] * bv[j];
        }
        __syncthreads();
    }

#pragma unroll
    for (int i = 0; i < TM; i++) {
        float4 v = make_float4(acc[i][0], acc[i][1], acc[i][2], acc[i][3]);
        *reinterpret_cast<float4*>(&Cj[(size_t)(m0 + trow * TM + i) * N + n0 + tcol * TN]) = v;
    }
}

// ---------------------------------------------------------------------------
// Inverse transform: out[i][t] = (1/8) * sum_j C2_j[i] * cos(2*pi*j*t/8),
// with C2_{8-j} = C2_j. Output is even in t: out_5=out_3, out_6=out_2, out_7=out_1.
// ---------------------------------------------------------------------------
__global__ void inv_transform_kernel(const float* __restrict__ C2,
                                     float* __restrict__ out,
                                     int n, size_t sstride) {
    int i = blockIdx.x * blockDim.x + threadIdx.x;
    if (i >= n) return;
    float g0 = C2[0 * sstride + i];
    float g1 = C2[1 * sstride + i];
    float g2 = C2[2 * sstride + i];
    float g3 = C2[3 * sstride + i];
    float g4 = C2[4 * sstride + i];

    float d13 = 2.0f * RSQ2 * (g1 - g3);
    float o0 = 0.125f * (g0 + 2.0f * (g1 + g2 + g3) + g4);
    float o1 = 0.125f * ((g0 - g4) + d13);
    float o2 = 0.125f * ((g0 + g4) - 2.0f * g2);
    float o3 = 0.125f * ((g0 - g4) - d13);
    float o4 = 0.125f * (g0 - 2.0f * (g1 - g2 + g3) + g4);

    reinterpret_cast<float4*>(out)[(size_t)2 * i]     = make_float4(o0, o1, o2, o3);
    reinterpret_cast<float4*>(out)[(size_t)2 * i + 1] = make_float4(o4, o3, o2, o1);
}

// ---------------------------------------------------------------------------
// kernel_launch
// ---------------------------------------------------------------------------
extern "C" void kernel_launch(void* const* d_in, const int* in_sizes, int n_in,
                              void* d_out, int out_size) {
    // Identify inputs by element count (robust to metadata ordering).
    const float* X = nullptr;  // (2048, 256, 8)
    const float* A = nullptr;  // (2048, 2048, 8)
    const float* W = nullptr;  // (256, 256, 8)
    for (int i = 0; i < n_in; i++) {
        if (in_sizes[i] == NN * NN * 8)      A = (const float*)d_in[i];
        else if (in_sizes[i] == NN * HH * 8) X = (const float*)d_in[i];
        else if (in_sizes[i] == HH * HH * 8) W = (const float*)d_in[i];
    }
    float* out = (float*)d_out;

    float *pAf, *pXf, *pWf, *pC1, *pC2;
    cudaGetSymbolAddress((void**)&pAf, g_Af);
    cudaGetSymbolAddress((void**)&pXf, g_Xf);
    cudaGetSymbolAddress((void**)&pWf, g_Wf);
    cudaGetSymbolAddress((void**)&pC1, g_C1);
    cudaGetSymbolAddress((void**)&pC2, g_C2);

    const int nX = NN * HH;   // 524288
    const int nW = HH * HH;   // 65536
    const int nA = NN * NN;   // 4194304

    fwd_transform_kernel<<<(nX + 255) / 256, 256>>>(X, pXf, nX, (size_t)nX);
    fwd_transform_kernel<<<(nW + 255) / 256, 256>>>(W, pWf, nW, (size_t)nW);
    fwd_transform_kernel<<<(nA + 255) / 256, 256>>>(A, pAf, nA, (size_t)nA);

    dim3 grid(HH / BN, NN / BM, NJ);   // (4, 16, 5)
    // C1_j = Af_j (2048x2048) @ Xf_j (2048x256)
    sgemm_kernel<<<grid, 256>>>(pAf, pXf, pC1, NN, HH, NN,
                                (size_t)NN * NN, (size_t)NN * HH, (size_t)NN * HH);
    // C2_j = C1_j (2048x256) @ Wf_j (256x256)
    sgemm_kernel<<<grid, 256>>>(pC1, pWf, pC2, NN, HH, HH,
                                (size_t)NN * HH, (size_t)HH * HH, (size_t)NN * HH);

    inv_transform_kernel<<<(nX + 255) / 256, 256>>>(pC2, out, nX, (size_t)nX);
}

// round 5
// speedup vs baseline: 1.0135x; 1.0135x over previous
#include <cuda_runtime.h>
#include <cuda_bf16.h>
#include <cstdint>

#define NN 2048
#define HH 256
#define NJ 5
#define RSQ2 0.70710678118654752440f

#define NA ((size_t)NN * NN)
#define NX ((size_t)NN * HH)
#define NW ((size_t)HH * HH)

__device__ unsigned short g_Ah[NJ * NA];
__device__ unsigned short g_Al[NJ * NA];
__device__ unsigned short g_Xh[NJ * NX];
__device__ unsigned short g_Xl[NJ * NX];
__device__ unsigned short g_Wh[NJ * NW];
__device__ unsigned short g_Wl[NJ * NW];
__device__ unsigned short g_C1h[NJ * NX];
__device__ unsigned short g_C1l[NJ * NX];
__device__ float          g_C2[NJ * NX];

__device__ __forceinline__ uint32_t smem_u32(const void* p) {
    uint32_t a;
    asm("{ .reg .u64 t; cvta.to.shared.u64 t, %1; cvt.u32.u64 %0, t; }"
        : "=r"(a) : "l"(p));
    return a;
}
__device__ __forceinline__ void cp16(uint32_t dst, const void* src) {
    asm volatile("cp.async.cg.shared.global [%0], [%1], 16;" :: "r"(dst), "l"(src));
}
__device__ __forceinline__ void ldsm4(uint32_t& r0, uint32_t& r1, uint32_t& r2,
                                      uint32_t& r3, uint32_t addr) {
    asm volatile("ldmatrix.sync.aligned.m8n8.x4.shared.b16 {%0,%1,%2,%3}, [%4];"
                 : "=r"(r0), "=r"(r1), "=r"(r2), "=r"(r3) : "r"(addr));
}
__device__ __forceinline__ void mma16816(float* d, const uint32_t* a,
                                         uint32_t b0, uint32_t b1) {
    asm volatile(
        "mma.sync.aligned.m16n8k16.row.col.f32.bf16.bf16.f32 "
        "{%0,%1,%2,%3}, {%4,%5,%6,%7}, {%8,%9}, {%0,%1,%2,%3};"
        : "+f"(d[0]), "+f"(d[1]), "+f"(d[2]), "+f"(d[3])
        : "r"(a[0]), "r"(a[1]), "r"(a[2]), "r"(a[3]), "r"(b0), "r"(b1));
}

__device__ __forceinline__ void cos5(float4 lo, float4 hi, float f[5]) {
    float s04 = lo.x + hi.x, d04 = lo.x - hi.x;
    float s26 = lo.z + hi.z;
    float s15 = lo.y + hi.y, d15 = lo.y - hi.y;
    float s37 = lo.w + hi.w, d37 = lo.w - hi.w;
    float t = RSQ2 * (d15 - d37);
    f[0] = (s04 + s26) + (s15 + s37);
    f[1] = d04 + t;
    f[2] = s04 - s26;
    f[3] = d04 - t;
    f[4] = (s04 + s26) - (s15 + s37);
}
__device__ __forceinline__ void split2(float f, unsigned short& h, unsigned short& l) {
    __nv_bfloat16 bh = __float2bfloat16(f);
    float r = f - __bfloat162float(bh);
    __nv_bfloat16 bl = __float2bfloat16(r);
    h = *reinterpret_cast<unsigned short*>(&bh);
    l = *reinterpret_cast<unsigned short*>(&bl);
}

// A: [n1][n2][8] -> Ah/Al [j][n1*NN+n2]; 4 elements per thread, 8B packed stores
__global__ void fwd_A_kernel(const float* __restrict__ in,
                             unsigned short* __restrict__ oh,
                             unsigned short* __restrict__ ol, size_t n) {
    size_t i0 = ((size_t)blockIdx.x * blockDim.x + threadIdx.x) * 4;
    if (i0 >= n) return;
    const float4* p = reinterpret_cast<const float4*>(in) + 2 * i0;
    unsigned short h[4][5], l[4][5];
#pragma unroll
    for (int e = 0; e < 4; e++) {
        float f[5]; cos5(p[2 * e], p[2 * e + 1], f);
#pragma unroll
        for (int j = 0; j < 5; j++) split2(f[j], h[e][j], l[e][j]);
    }
#pragma unroll
    for (int j = 0; j < 5; j++) {
        uint2 vh = make_uint2((uint32_t)h[0][j] | ((uint32_t)h[1][j] << 16),
                              (uint32_t)h[2][j] | ((uint32_t)h[3][j] << 16));
        uint2 vl = make_uint2((uint32_t)l[0][j] | ((uint32_t)l[1][j] << 16),
                              (uint32_t)l[2][j] | ((uint32_t)l[3][j] << 16));
        *reinterpret_cast<uint2*>(oh + j * n + i0) = vh;
        *reinterpret_cast<uint2*>(ol + j * n + i0) = vl;
    }
}

// src [R][C][8] -> out [j][C][R]  (transpose + cos + split)
__global__ void fwd_T_kernel(const float* __restrict__ in,
                             unsigned short* __restrict__ oh,
                             unsigned short* __restrict__ ol,
                             int R, int C) {
    int i = blockIdx.x * blockDim.x + threadIdx.x;
    size_t n = (size_t)R * C;
    if (i >= (int)n) return;
    int c = i / R, r = i - c * R;
    const float4* p = reinterpret_cast<const float4*>(in) + 2 * ((size_t)r * C + c);
    float f[5]; cos5(p[0], p[1], f);
#pragma unroll
    for (int j = 0; j < 5; j++) {
        unsigned short h, l; split2(f[j], h, l);
        oh[j * n + i] = h; ol[j * n + i] = l;
    }
}

__global__ void inv_kernel(const float* __restrict__ C2,
                           float* __restrict__ out, int n, size_t ss) {
    int i = blockIdx.x * blockDim.x + threadIdx.x;
    if (i >= n) return;
    float g0 = C2[0 * ss + i], g1 = C2[1 * ss + i], g2 = C2[2 * ss + i];
    float g3 = C2[3 * ss + i], g4 = C2[4 * ss + i];
    float d13 = 2.0f * RSQ2 * (g1 - g3);
    float o0 = 0.125f * (g0 + 2.0f * (g1 + g2 + g3) + g4);
    float o1 = 0.125f * ((g0 - g4) + d13);
    float o2 = 0.125f * ((g0 + g4) - 2.0f * g2);
    float o3 = 0.125f * ((g0 - g4) - d13);
    float o4 = 0.125f * (g0 - 2.0f * (g1 - g2 + g3) + g4);
    reinterpret_cast<float4*>(out)[(size_t)2 * i]     = make_float4(o0, o1, o2, o3);
    reinterpret_cast<float4*>(out)[(size_t)2 * i + 1] = make_float4(o4, o3, o2, o1);
}

// C[128,128 tile] fp32 = sum over virtual K' = 3K of Aseg[m,k]*Bseg[n,k] (bf16)
// Segments: (Ah,Bh), (Ah,Bl), (Al,Bh).  K-chunk = 64 bf16 (128B rows).
// 512 threads, 16 warps in 4x4 grid, warp tile 32x32 -> 32 accum regs/thread.
#define BM 128
#define BN 128
#define ASTG (BM * 128)
#define BSTG (BN * 128)
#define STGB (ASTG + BSTG)
#define STAGES 3
#define GSMEM (STAGES * STGB)
#define NTHR 512

__device__ __forceinline__ uint32_t swz(int row, int cbyte) {
    return (uint32_t)(row * 128 + (cbyte ^ ((row & 7) << 4)));
}

template <bool SPLIT_OUT>
__global__ __launch_bounds__(NTHR, 2) void gemm_kernel(
    const unsigned short* __restrict__ Ah, const unsigned short* __restrict__ Al,
    int lda, size_t sA,
    const unsigned short* __restrict__ Bh, const unsigned short* __restrict__ Bl,
    int ldb, size_t sB,
    unsigned short* __restrict__ outH, unsigned short* __restrict__ outL,
    float* __restrict__ outF,
    int NT, int segChunks)
{
    extern __shared__ char smem[];
    const uint32_t sbase = smem_u32(smem);
    const int tid = threadIdx.x;
    const int wid = tid >> 5;
    const int lane = tid & 31;
    const int slice = blockIdx.z;
    const int m0 = blockIdx.x * BM;
    const int n0 = blockIdx.y * BN;

    Ah += slice * sA;  Al += slice * sA;
    Bh += slice * sB;  Bl += slice * sB;

    const int lrow = tid >> 3;          // 0..63
    const int lc16 = (tid & 7) << 4;    // byte col 0..112
    auto load_stage = [&](int s, int ktl) {
        int seg = ktl / segChunks;
        int kk = (ktl - seg * segChunks) * 64;
        const unsigned short* As = (seg < 2) ? Ah : Al;
        const unsigned short* Bs = (seg == 1) ? Bl : Bh;
        uint32_t ab = sbase + s * STGB;
        uint32_t bb = ab + ASTG;
#pragma unroll
        for (int t = 0; t < 2; t++) {
            int row = lrow + t * 64;
            cp16(ab + swz(row, lc16), As + (size_t)(m0 + row) * lda + kk + (lc16 >> 1));
        }
#pragma unroll
        for (int t = 0; t < 2; t++) {
            int row = lrow + t * 64;
            cp16(bb + swz(row, lc16), Bs + (size_t)(n0 + row) * ldb + kk + (lc16 >> 1));
        }
        asm volatile("cp.async.commit_group;" ::: "memory");
    };

    // warp tiling: 4 (M) x 4 (N) warps, warp tile 32x32
    const int wm = (wid >> 2) * 32;
    const int wn = (wid & 3) * 32;

    float d[2][4][4];
#pragma unroll
    for (int i = 0; i < 2; i++)
#pragma unroll
        for (int j = 0; j < 4; j++)
#pragma unroll
            for (int r = 0; r < 4; r++) d[i][j][r] = 0.0f;

    const int aRow = wm + (lane & 7) + ((lane >> 3) & 1) * 8;   // + f*16
    const int aC16 = ((lane >> 4) & 1) * 16;                     // + s*32
    const int bRow = wn + (lane & 7) + ((lane >> 4) & 1) * 8;   // + p*16
    const int bC16 = ((lane >> 3) & 1) * 16;                     // + s*32

    load_stage(0, 0);
    if (NT > 1) load_stage(1, 1);

    for (int kt = 0; kt < NT; ++kt) {
        if (kt + 1 < NT) asm volatile("cp.async.wait_group 1;" ::: "memory");
        else             asm volatile("cp.async.wait_group 0;" ::: "memory");
        __syncthreads();
        if (kt + 2 < NT) load_stage((kt + 2) % STAGES, kt + 2);

        uint32_t ab = sbase + (kt % STAGES) * STGB;
        uint32_t bb = ab + ASTG;

#pragma unroll
        for (int s = 0; s < 4; s++) {
            uint32_t a[2][4];
#pragma unroll
            for (int f = 0; f < 2; f++) {
                int row = aRow + f * 16;
                ldsm4(a[f][0], a[f][1], a[f][2], a[f][3],
                      ab + swz(row, s * 32 + aC16));
            }
            uint32_t b[2][4];
#pragma unroll
            for (int p = 0; p < 2; p++) {
                int row = bRow + p * 16;
                ldsm4(b[p][0], b[p][1], b[p][2], b[p][3],
                      bb + swz(row, s * 32 + bC16));
            }
#pragma unroll
            for (int mf = 0; mf < 2; mf++)
#pragma unroll
                for (int nf = 0; nf < 4; nf++) {
                    int p = nf >> 1, h = nf & 1;
                    mma16816(d[mf][nf], a[mf], b[p][h * 2], b[p][h * 2 + 1]);
                }
        }
    }

    const int q = lane >> 2;
    const int cp2 = (lane & 3) * 2;
#pragma unroll
    for (int mf = 0; mf < 2; mf++) {
#pragma unroll
        for (int nf = 0; nf < 4; nf++) {
            int row = m0 + wm + mf * 16 + q;
            int col = n0 + wn + nf * 8 + cp2;
            if (SPLIT_OUT) {
#pragma unroll
                for (int half = 0; half < 2; half++) {
                    float v0 = d[mf][nf][half * 2];
                    float v1 = d[mf][nf][half * 2 + 1];
                    unsigned short h0, l0, h1, l1;
                    split2(v0, h0, l0); split2(v1, h1, l1);
                    size_t off = slice * NX + (size_t)(row + half * 8) * HH + col;
                    *reinterpret_cast<uint32_t*>(outH + off) =
                        (uint32_t)h0 | ((uint32_t)h1 << 16);
                    *reinterpret_cast<uint32_t*>(outL + off) =
                        (uint32_t)l0 | ((uint32_t)l1 << 16);
                }
            } else {
#pragma unroll
                for (int half = 0; half < 2; half++) {
                    size_t off = slice * NX + (size_t)(row + half * 8) * HH + col;
                    *reinterpret_cast<float2*>(outF + off) =
                        make_float2(d[mf][nf][half * 2], d[mf][nf][half * 2 + 1]);
                }
            }
        }
    }
}

extern "C" void kernel_launch(void* const* d_in, const int* in_sizes, int n_in,
                              void* d_out, int out_size) {
    const float* X = nullptr; const float* A = nullptr; const float* W = nullptr;
    for (int i = 0; i < n_in; i++) {
        if (in_sizes[i] == NN * NN * 8)      A = (const float*)d_in[i];
        else if (in_sizes[i] == NN * HH * 8) X = (const float*)d_in[i];
        else if (in_sizes[i] == HH * HH * 8) W = (const float*)d_in[i];
    }
    float* out = (float*)d_out;

    unsigned short *pAh, *pAl, *pXh, *pXl, *pWh, *pWl, *pC1h, *pC1l;
    float* pC2;
    cudaGetSymbolAddress((void**)&pAh, g_Ah);
    cudaGetSymbolAddress((void**)&pAl, g_Al);
    cudaGetSymbolAddress((void**)&pXh, g_Xh);
    cudaGetSymbolAddress((void**)&pXl, g_Xl);
    cudaGetSymbolAddress((void**)&pWh, g_Wh);
    cudaGetSymbolAddress((void**)&pWl, g_Wl);
    cudaGetSymbolAddress((void**)&pC1h, g_C1h);
    cudaGetSymbolAddress((void**)&pC1l, g_C1l);
    cudaGetSymbolAddress((void**)&pC2, g_C2);

    cudaFuncSetAttribute(gemm_kernel<true>,
                         cudaFuncAttributeMaxDynamicSharedMemorySize, GSMEM);
    cudaFuncSetAttribute(gemm_kernel<false>,
                         cudaFuncAttributeMaxDynamicSharedMemorySize, GSMEM);

    fwd_A_kernel<<<(int)(NA / 4 / 256), 256>>>(A, pAh, pAl, NA);
    fwd_T_kernel<<<(int)((NX + 255) / 256), 256>>>(X, pXh, pXl, NN, HH);
    fwd_T_kernel<<<(int)((NW + 255) / 256), 256>>>(W, pWh, pWl, HH, HH);

    dim3 grid(NN / BM, HH / BN, NJ);   // (16, 2, 5)
    gemm_kernel<true><<<grid, NTHR, GSMEM>>>(
        pAh, pAl, NN, NA, pXh, pXl, NN, NX, pC1h, pC1l, nullptr, 96, 32);
    gemm_kernel<false><<<grid, NTHR, GSMEM>>>(
        pC1h, pC1l, HH, NX, pWh, pWl, HH, NW, nullptr, nullptr, pC2, 12, 4);

    inv_kernel<<<(int)((NX + 255) / 256), 256>>>(pC2, out, (int)NX, NX);
}

// round 7
// speedup vs baseline: 2.1045x; 2.0765x over previous
#include <cuda_runtime.h>
#include <cuda_bf16.h>
#include <cstdint>

#define NN 2048
#define HH 256
#define NJ 5
#define RSQ2 0.70710678118654752440f

#define NA ((size_t)NN * NN)
#define NX ((size_t)NN * HH)
#define NW ((size_t)HH * HH)

__device__ unsigned short g_Ah[NJ * NA];
__device__ unsigned short g_Al[NJ * NA];
__device__ unsigned short g_Xh[NJ * NX];
__device__ unsigned short g_Xl[NJ * NX];
__device__ unsigned short g_Wh[NJ * NW];
__device__ unsigned short g_Wl[NJ * NW];
__device__ unsigned short g_C1h[NJ * NX];
__device__ unsigned short g_C1l[NJ * NX];
__device__ float          g_P1[2 * NJ * NX];   // split-K partials of GEMM1
__device__ float          g_P2[2 * NJ * NX];   // split-K partials of GEMM2

__device__ __forceinline__ uint32_t smem_u32(const void* p) {
    uint32_t a;
    asm("{ .reg .u64 t; cvta.to.shared.u64 t, %1; cvt.u32.u64 %0, t; }"
        : "=r"(a) : "l"(p));
    return a;
}
__device__ __forceinline__ void cp16(uint32_t dst, const void* src) {
    asm volatile("cp.async.cg.shared.global [%0], [%1], 16;" :: "r"(dst), "l"(src));
}
__device__ __forceinline__ void ldsm4(uint32_t& r0, uint32_t& r1, uint32_t& r2,
                                      uint32_t& r3, uint32_t addr) {
    asm volatile("ldmatrix.sync.aligned.m8n8.x4.shared.b16 {%0,%1,%2,%3}, [%4];"
                 : "=r"(r0), "=r"(r1), "=r"(r2), "=r"(r3) : "r"(addr));
}
__device__ __forceinline__ void mma16816(float* d, const uint32_t* a,
                                         uint32_t b0, uint32_t b1) {
    asm volatile(
        "mma.sync.aligned.m16n8k16.row.col.f32.bf16.bf16.f32 "
        "{%0,%1,%2,%3}, {%4,%5,%6,%7}, {%8,%9}, {%0,%1,%2,%3};"
        : "+f"(d[0]), "+f"(d[1]), "+f"(d[2]), "+f"(d[3])
        : "r"(a[0]), "r"(a[1]), "r"(a[2]), "r"(a[3]), "r"(b0), "r"(b1));
}

__device__ __forceinline__ void cos5(float4 lo, float4 hi, float f[5]) {
    float s04 = lo.x + hi.x, d04 = lo.x - hi.x;
    float s26 = lo.z + hi.z;
    float s15 = lo.y + hi.y, d15 = lo.y - hi.y;
    float s37 = lo.w + hi.w, d37 = lo.w - hi.w;
    float t = RSQ2 * (d15 - d37);
    f[0] = (s04 + s26) + (s15 + s37);
    f[1] = d04 + t;
    f[2] = s04 - s26;
    f[3] = d04 - t;
    f[4] = (s04 + s26) - (s15 + s37);
}
__device__ __forceinline__ void split2(float f, unsigned short& h, unsigned short& l) {
    __nv_bfloat16 bh = __float2bfloat16(f);
    float r = f - __bfloat162float(bh);
    __nv_bfloat16 bl = __float2bfloat16(r);
    h = *reinterpret_cast<unsigned short*>(&bh);
    l = *reinterpret_cast<unsigned short*>(&bl);
}

// A: [n1][n2][8] -> Ah/Al [j][n1*NN+n2]; 4 elements/thread, 8B packed stores
__global__ void fwd_A_kernel(const float* __restrict__ in,
                             unsigned short* __restrict__ oh,
                             unsigned short* __restrict__ ol, size_t n) {
    size_t i0 = ((size_t)blockIdx.x * blockDim.x + threadIdx.x) * 4;
    if (i0 >= n) return;
    const float4* p = reinterpret_cast<const float4*>(in) + 2 * i0;
    unsigned short h[4][5], l[4][5];
#pragma unroll
    for (int e = 0; e < 4; e++) {
        float f[5]; cos5(p[2 * e], p[2 * e + 1], f);
#pragma unroll
        for (int j = 0; j < 5; j++) split2(f[j], h[e][j], l[e][j]);
    }
#pragma unroll
    for (int j = 0; j < 5; j++) {
        uint2 vh = make_uint2((uint32_t)h[0][j] | ((uint32_t)h[1][j] << 16),
                              (uint32_t)h[2][j] | ((uint32_t)h[3][j] << 16));
        uint2 vl = make_uint2((uint32_t)l[0][j] | ((uint32_t)l[1][j] << 16),
                              (uint32_t)l[2][j] | ((uint32_t)l[3][j] << 16));
        *reinterpret_cast<uint2*>(oh + j * n + i0) = vh;
        *reinterpret_cast<uint2*>(ol + j * n + i0) = vl;
    }
}

// src [R][C][8] -> out [j][C][R]  (transpose + cos + split)
__global__ void fwd_T_kernel(const float* __restrict__ in,
                             unsigned short* __restrict__ oh,
                             unsigned short* __restrict__ ol,
                             int R, int C) {
    int i = blockIdx.x * blockDim.x + threadIdx.x;
    size_t n = (size_t)R * C;
    if (i >= (int)n) return;
    int c = i / R, r = i - c * R;
    const float4* p = reinterpret_cast<const float4*>(in) + 2 * ((size_t)r * C + c);
    float f[5]; cos5(p[0], p[1], f);
#pragma unroll
    for (int j = 0; j < 5; j++) {
        unsigned short h, l; split2(f[j], h, l);
        oh[j * n + i] = h; ol[j * n + i] = l;
    }
}

// sum split-K partials of GEMM1, split into bf16 hi/lo for GEMM2
__global__ void reduce_split_kernel(const float* __restrict__ P,
                                    unsigned short* __restrict__ oh,
                                    unsigned short* __restrict__ ol) {
    size_t i0 = ((size_t)blockIdx.x * blockDim.x + threadIdx.x) * 4;
    size_t slice = i0 / NX;
    size_t r = i0 - slice * NX;
    const float4 v0 = *reinterpret_cast<const float4*>(P + (2 * slice) * NX + r);
    const float4 v1 = *reinterpret_cast<const float4*>(P + (2 * slice + 1) * NX + r);
    float s[4] = {v0.x + v1.x, v0.y + v1.y, v0.z + v1.z, v0.w + v1.w};
    unsigned short h[4], l[4];
#pragma unroll
    for (int e = 0; e < 4; e++) split2(s[e], h[e], l[e]);
    *reinterpret_cast<uint2*>(oh + i0) =
        make_uint2((uint32_t)h[0] | ((uint32_t)h[1] << 16),
                   (uint32_t)h[2] | ((uint32_t)h[3] << 16));
    *reinterpret_cast<uint2*>(ol + i0) =
        make_uint2((uint32_t)l[0] | ((uint32_t)l[1] << 16),
                   (uint32_t)l[2] | ((uint32_t)l[3] << 16));
}

// inverse cos transform; also folds the GEMM2 split-K reduction
__global__ void inv_kernel(const float* __restrict__ P2,
                           float* __restrict__ out, int n) {
    int i = blockIdx.x * blockDim.x + threadIdx.x;
    if (i >= n) return;
    float g[5];
#pragma unroll
    for (int j = 0; j < 5; j++)
        g[j] = P2[(size_t)(2 * j) * NX + i] + P2[(size_t)(2 * j + 1) * NX + i];
    float d13 = 2.0f * RSQ2 * (g[1] - g[3]);
    float o0 = 0.125f * (g[0] + 2.0f * (g[1] + g[2] + g[3]) + g[4]);
    float o1 = 0.125f * ((g[0] - g[4]) + d13);
    float o2 = 0.125f * ((g[0] + g[4]) - 2.0f * g[2]);
    float o3 = 0.125f * ((g[0] - g[4]) - d13);
    float o4 = 0.125f * (g[0] - 2.0f * (g[1] - g[2] + g[3]) + g[4]);
    reinterpret_cast<float4*>(out)[(size_t)2 * i]     = make_float4(o0, o1, o2, o3);
    reinterpret_cast<float4*>(out)[(size_t)2 * i + 1] = make_float4(o4, o3, o2, o1);
}

// ---------------- mma.sync split-GEMM with split-K --------------------------
// blockIdx.z = 2*slice + half; each CTA accumulates nHalf virtual-K chunks
// into its own fp32 partial buffer slab (z*NX).
// Segments over full K': (Ah,Bh), (Ah,Bl), (Al,Bh). K-chunk = 64 bf16.
#define BM 128
#define BN 128
#define ASTG (BM * 128)
#define BSTG (BN * 128)
#define STGB (ASTG + BSTG)
#define STAGES 3
#define GSMEM (STAGES * STGB)

__device__ __forceinline__ uint32_t swz(int row, int cbyte) {
    return (uint32_t)(row * 128 + (cbyte ^ ((row & 7) << 4)));
}

__global__ __launch_bounds__(256) void gemm_kernel(
    const unsigned short* __restrict__ Ah, const unsigned short* __restrict__ Al,
    int lda, size_t sA,
    const unsigned short* __restrict__ Bh, const unsigned short* __restrict__ Bl,
    int ldb, size_t sB,
    float* __restrict__ outP,
    int nHalf, int segChunks)
{
    extern __shared__ char smem[];
    const uint32_t sbase = smem_u32(smem);
    const int tid = threadIdx.x;
    const int wid = tid >> 5;
    const int lane = tid & 31;
    const int z = blockIdx.z;
    const int slice = z >> 1;
    const int ktBegin = (z & 1) * nHalf;
    const int ktEnd = ktBegin + nHalf;
    const int m0 = blockIdx.x * BM;
    const int n0 = blockIdx.y * BN;

    Ah += slice * sA;  Al += slice * sA;
    Bh += slice * sB;  Bl += slice * sB;
    outP += (size_t)z * NX;

    const int lrow = tid >> 3;          // 0..31
    const int lc16 = (tid & 7) << 4;    // byte col 0..112
    auto load_stage = [&](int s, int ktl) {
        int seg = ktl / segChunks;
        int kk = (ktl - seg * segChunks) * 64;
        const unsigned short* As = (seg < 2) ? Ah : Al;
        const unsigned short* Bs = (seg == 1) ? Bl : Bh;
        uint32_t ab = sbase + s * STGB;
        uint32_t bb = ab + ASTG;
#pragma unroll
        for (int t = 0; t < 4; t++) {
            int row = lrow + t * 32;
            cp16(ab + swz(row, lc16), As + (size_t)(m0 + row) * lda + kk + (lc16 >> 1));
        }
#pragma unroll
        for (int t = 0; t < 4; t++) {
            int row = lrow + t * 32;
            cp16(bb + swz(row, lc16), Bs + (size_t)(n0 + row) * ldb + kk + (lc16 >> 1));
        }
        asm volatile("cp.async.commit_group;" ::: "memory");
    };

    // warp tiling: 2 (M) x 4 (N) warps, warp tile 64x32
    const int wm = (wid >> 2) * 64;
    const int wn = (wid & 3) * 32;

    float d[4][4][4];
#pragma unroll
    for (int i = 0; i < 4; i++)
#pragma unroll
        for (int j = 0; j < 4; j++)
#pragma unroll
            for (int r = 0; r < 4; r++) d[i][j][r] = 0.0f;

    const int aRow = wm + (lane & 7) + ((lane >> 3) & 1) * 8;   // + f*16
    const int aC16 = ((lane >> 4) & 1) * 16;                     // + s*32
    const int bRow = wn + (lane & 7) + ((lane >> 4) & 1) * 8;   // + p*16
    const int bC16 = ((lane >> 3) & 1) * 16;                     // + s*32

    load_stage(0, ktBegin);
    if (ktBegin + 1 < ktEnd) load_stage(1, ktBegin + 1);

    for (int kt = ktBegin; kt < ktEnd; ++kt) {
        if (kt + 1 < ktEnd) asm volatile("cp.async.wait_group 1;" ::: "memory");
        else                asm volatile("cp.async.wait_group 0;" ::: "memory");
        __syncthreads();
        if (kt + 2 < ktEnd) load_stage((kt + 2 - ktBegin) % STAGES, kt + 2);

        uint32_t ab = sbase + ((kt - ktBegin) % STAGES) * STGB;
        uint32_t bb = ab + ASTG;

#pragma unroll
        for (int s = 0; s < 4; s++) {
            uint32_t a[4][4];
#pragma unroll
            for (int f = 0; f < 4; f++) {
                int row = aRow + f * 16;
                ldsm4(a[f][0], a[f][1], a[f][2], a[f][3],
                      ab + swz(row, s * 32 + aC16));
            }
            uint32_t b[2][4];
#pragma unroll
            for (int p = 0; p < 2; p++) {
                int row = bRow + p * 16;
                ldsm4(b[p][0], b[p][1], b[p][2], b[p][3],
                      bb + swz(row, s * 32 + bC16));
            }
#pragma unroll
            for (int mf = 0; mf < 4; mf++)
#pragma unroll
                for (int nf = 0; nf < 4; nf++) {
                    int p = nf >> 1, h = nf & 1;
                    mma16816(d[mf][nf], a[mf], b[p][h * 2], b[p][h * 2 + 1]);
                }
        }
    }

    const int q = lane >> 2;
    const int cp2 = (lane & 3) * 2;
#pragma unroll
    for (int mf = 0; mf < 4; mf++) {
#pragma unroll
        for (int nf = 0; nf < 4; nf++) {
            int row = m0 + wm + mf * 16 + q;
            int col = n0 + wn + nf * 8 + cp2;
#pragma unroll
            for (int half = 0; half < 2; half++) {
                size_t off = (size_t)(row + half * 8) * HH + col;
                *reinterpret_cast<float2*>(outP + off) =
                    make_float2(d[mf][nf][half * 2], d[mf][nf][half * 2 + 1]);
            }
        }
    }
}

extern "C" void kernel_launch(void* const* d_in, const int* in_sizes, int n_in,
                              void* d_out, int out_size) {
    const float* X = nullptr; const float* A = nullptr; const float* W = nullptr;
    for (int i = 0; i < n_in; i++) {
        if (in_sizes[i] == NN * NN * 8)      A = (const float*)d_in[i];
        else if (in_sizes[i] == NN * HH * 8) X = (const float*)d_in[i];
        else if (in_sizes[i] == HH * HH * 8) W = (const float*)d_in[i];
    }
    float* out = (float*)d_out;

    unsigned short *pAh, *pAl, *pXh, *pXl, *pWh, *pWl, *pC1h, *pC1l;
    float *pP1, *pP2;
    cudaGetSymbolAddress((void**)&pAh, g_Ah);
    cudaGetSymbolAddress((void**)&pAl, g_Al);
    cudaGetSymbolAddress((void**)&pXh, g_Xh);
    cudaGetSymbolAddress((void**)&pXl, g_Xl);
    cudaGetSymbolAddress((void**)&pWh, g_Wh);
    cudaGetSymbolAddress((void**)&pWl, g_Wl);
    cudaGetSymbolAddress((void**)&pC1h, g_C1h);
    cudaGetSymbolAddress((void**)&pC1l, g_C1l);
    cudaGetSymbolAddress((void**)&pP1, g_P1);
    cudaGetSymbolAddress((void**)&pP2, g_P2);

    cudaFuncSetAttribute(gemm_kernel,
                         cudaFuncAttributeMaxDynamicSharedMemorySize, GSMEM);

    fwd_A_kernel<<<(int)(NA / 4 / 256), 256>>>(A, pAh, pAl, NA);
    fwd_T_kernel<<<(int)((NX + 255) / 256), 256>>>(X, pXh, pXl, NN, HH);
    fwd_T_kernel<<<(int)((NW + 255) / 256), 256>>>(W, pWh, pWl, HH, HH);

    // GEMM1: K' = 96 chunks, split-K2 -> 48 per half; grid (16,2,10) = 320 CTAs
    dim3 grid(NN / BM, HH / BN, 2 * NJ);
    gemm_kernel<<<grid, 256, GSMEM>>>(
        pAh, pAl, NN, NA, pXh, pXl, NN, NX, pP1, 48, 32);

    // reduce GEMM1 partials -> C1 hi/lo
    reduce_split_kernel<<<(int)(NJ * NX / 4 / 256), 256>>>(pP1, pC1h, pC1l);

    // GEMM2: K' = 12 chunks, split-K2 -> 6 per half
    gemm_kernel<<<grid, 256, GSMEM>>>(
        pC1h, pC1l, HH, NX, pWh, pWl, HH, NW, pP2, 6, 4);

    // inverse transform (folds GEMM2 partial reduction)
    inv_kernel<<<(int)((NX + 255) / 256), 256>>>(pP2, out, (int)NX);
}

// round 8
// speedup vs baseline: 3.9098x; 1.8578x over previous
#include <cuda_runtime.h>
#include <cuda_fp16.h>
#include <cstdint>

#define NN 2048
#define HH 256
#define NJ 5
#define RSQ2 0.70710678118654752440f

#define NA ((size_t)NN * NN)
#define NX ((size_t)NN * HH)
#define NW ((size_t)HH * HH)

// fp16 operands stored as ushort
__device__ unsigned short g_Af[NJ * NA];   // 41.9 MB  [j][node][k]
__device__ unsigned short g_Xf[NJ * NX];   //  5.2 MB  [j][hidden][node] (B layout [n][k])
__device__ unsigned short g_Wf[NJ * NW];   //  0.65 MB [j][h_out][h_in]  (B layout [n][k])
__device__ unsigned short g_C1[NJ * NX];   //  5.2 MB  [j][node][h]
__device__ float          g_P1[4 * NJ * NX];  // 42 MB: GEMM1 split-K4 partials
__device__ float          g_P2[NJ * NX];      // 10.5 MB: GEMM2 result

__device__ __forceinline__ uint32_t smem_u32(const void* p) {
    uint32_t a;
    asm("{ .reg .u64 t; cvta.to.shared.u64 t, %1; cvt.u32.u64 %0, t; }"
        : "=r"(a) : "l"(p));
    return a;
}
__device__ __forceinline__ void cp16(uint32_t dst, const void* src) {
    asm volatile("cp.async.cg.shared.global [%0], [%1], 16;" :: "r"(dst), "l"(src));
}
__device__ __forceinline__ void ldsm4(uint32_t& r0, uint32_t& r1, uint32_t& r2,
                                      uint32_t& r3, uint32_t addr) {
    asm volatile("ldmatrix.sync.aligned.m8n8.x4.shared.b16 {%0,%1,%2,%3}, [%4];"
                 : "=r"(r0), "=r"(r1), "=r"(r2), "=r"(r3) : "r"(addr));
}
__device__ __forceinline__ void mma16816(float* d, const uint32_t* a,
                                         uint32_t b0, uint32_t b1) {
    asm volatile(
        "mma.sync.aligned.m16n8k16.row.col.f32.f16.f16.f32 "
        "{%0,%1,%2,%3}, {%4,%5,%6,%7}, {%8,%9}, {%0,%1,%2,%3};"
        : "+f"(d[0]), "+f"(d[1]), "+f"(d[2]), "+f"(d[3])
        : "r"(a[0]), "r"(a[1]), "r"(a[2]), "r"(a[3]), "r"(b0), "r"(b1));
}

__device__ __forceinline__ void cos5(float4 lo, float4 hi, float f[5]) {
    float s04 = lo.x + hi.x, d04 = lo.x - hi.x;
    float s26 = lo.z + hi.z;
    float s15 = lo.y + hi.y, d15 = lo.y - hi.y;
    float s37 = lo.w + hi.w, d37 = lo.w - hi.w;
    float t = RSQ2 * (d15 - d37);
    f[0] = (s04 + s26) + (s15 + s37);
    f[1] = d04 + t;
    f[2] = s04 - s26;
    f[3] = d04 - t;
    f[4] = (s04 + s26) - (s15 + s37);
}
__device__ __forceinline__ unsigned short h16(float f) {
    __half h = __float2half_rn(f);
    return *reinterpret_cast<unsigned short*>(&h);
}

// A: [n1][n2][8] -> Af [j][n1*NN+n2] fp16; 4 elements/thread, 8B stores
__global__ void fwd_A_kernel(const float* __restrict__ in,
                             unsigned short* __restrict__ o, size_t n) {
    size_t i0 = ((size_t)blockIdx.x * blockDim.x + threadIdx.x) * 4;
    if (i0 >= n) return;
    const float4* p = reinterpret_cast<const float4*>(in) + 2 * i0;
    unsigned short h[4][5];
#pragma unroll
    for (int e = 0; e < 4; e++) {
        float f[5]; cos5(p[2 * e], p[2 * e + 1], f);
#pragma unroll
        for (int j = 0; j < 5; j++) h[e][j] = h16(f[j]);
    }
#pragma unroll
    for (int j = 0; j < 5; j++) {
        *reinterpret_cast<uint2*>(o + j * n + i0) =
            make_uint2((uint32_t)h[0][j] | ((uint32_t)h[1][j] << 16),
                       (uint32_t)h[2][j] | ((uint32_t)h[3][j] << 16));
    }
}

// src [R][C][8] -> out [j][C][R] fp16 (transpose + cos)
__global__ void fwd_T_kernel(const float* __restrict__ in,
                             unsigned short* __restrict__ o,
                             int R, int C) {
    int i = blockIdx.x * blockDim.x + threadIdx.x;
    size_t n = (size_t)R * C;
    if (i >= (int)n) return;
    int c = i / R, r = i - c * R;
    const float4* p = reinterpret_cast<const float4*>(in) + 2 * ((size_t)r * C + c);
    float f[5]; cos5(p[0], p[1], f);
#pragma unroll
    for (int j = 0; j < 5; j++) o[j * n + i] = h16(f[j]);
}

// sum 4 split-K partials of GEMM1 -> fp16 C1
__global__ void reduce4_kernel(const float* __restrict__ P,
                               unsigned short* __restrict__ o) {
    size_t i0 = ((size_t)blockIdx.x * blockDim.x + threadIdx.x) * 4;
    size_t slice = i0 / NX;
    size_t r = i0 - slice * NX;
    const float* base = P + 4 * slice * NX + r;
    float4 s = *reinterpret_cast<const float4*>(base);
#pragma unroll
    for (int q = 1; q < 4; q++) {
        float4 v = *reinterpret_cast<const float4*>(base + q * NX);
        s.x += v.x; s.y += v.y; s.z += v.z; s.w += v.w;
    }
    *reinterpret_cast<uint2*>(o + i0) =
        make_uint2((uint32_t)h16(s.x) | ((uint32_t)h16(s.y) << 16),
                   (uint32_t)h16(s.z) | ((uint32_t)h16(s.w) << 16));
}

// inverse cos transform over the 5 GEMM2 result slabs
__global__ void inv_kernel(const float* __restrict__ P2,
                           float* __restrict__ out, int n) {
    int i = blockIdx.x * blockDim.x + threadIdx.x;
    if (i >= n) return;
    float g[5];
#pragma unroll
    for (int j = 0; j < 5; j++) g[j] = P2[(size_t)j * NX + i];
    float d13 = 2.0f * RSQ2 * (g[1] - g[3]);
    float o0 = 0.125f * (g[0] + 2.0f * (g[1] + g[2] + g[3]) + g[4]);
    float o1 = 0.125f * ((g[0] - g[4]) + d13);
    float o2 = 0.125f * ((g[0] + g[4]) - 2.0f * g[2]);
    float o3 = 0.125f * ((g[0] - g[4]) - d13);
    float o4 = 0.125f * (g[0] - 2.0f * (g[1] - g[2] + g[3]) + g[4]);
    reinterpret_cast<float4*>(out)[(size_t)2 * i]     = make_float4(o0, o1, o2, o3);
    reinterpret_cast<float4*>(out)[(size_t)2 * i + 1] = make_float4(o4, o3, o2, o1);
}

// ---------------- fp16 mma.sync GEMM, optional split-K ----------------------
// blockIdx.z = slice*splitCnt + part; CTA does nPer K-chunks (64 each) into
// its own fp32 slab outP + z*NX.
#define BM 128
#define BN 128
#define ASTG (BM * 128)
#define BSTG (BN * 128)
#define STGB (ASTG + BSTG)
#define STAGES 3
#define GSMEM (STAGES * STGB)

__device__ __forceinline__ uint32_t swz(int row, int cbyte) {
    return (uint32_t)(row * 128 + (cbyte ^ ((row & 7) << 4)));
}

__global__ __launch_bounds__(256) void gemm_kernel(
    const unsigned short* __restrict__ A, int lda, size_t sA,
    const unsigned short* __restrict__ B, int ldb, size_t sB,
    float* __restrict__ outP, int nPer, int splitCnt)
{
    extern __shared__ char smem[];
    const uint32_t sbase = smem_u32(smem);
    const int tid = threadIdx.x;
    const int wid = tid >> 5;
    const int lane = tid & 31;
    const int z = blockIdx.z;
    const int slice = z / splitCnt;
    const int part = z - slice * splitCnt;
    const int ktBegin = part * nPer;
    const int ktEnd = ktBegin + nPer;
    const int m0 = blockIdx.x * BM;
    const int n0 = blockIdx.y * BN;

    A += slice * sA;
    B += slice * sB;
    outP += (size_t)z * NX;

    const int lrow = tid >> 3;          // 0..31
    const int lc16 = (tid & 7) << 4;    // byte col 0..112
    auto load_stage = [&](int s, int ktl) {
        int kk = ktl * 64;
        uint32_t ab = sbase + s * STGB;
        uint32_t bb = ab + ASTG;
#pragma unroll
        for (int t = 0; t < 4; t++) {
            int row = lrow + t * 32;
            cp16(ab + swz(row, lc16), A + (size_t)(m0 + row) * lda + kk + (lc16 >> 1));
        }
#pragma unroll
        for (int t = 0; t < 4; t++) {
            int row = lrow + t * 32;
            cp16(bb + swz(row, lc16), B + (size_t)(n0 + row) * ldb + kk + (lc16 >> 1));
        }
        asm volatile("cp.async.commit_group;" ::: "memory");
    };

    // warp tiling: 2 (M) x 4 (N) warps, warp tile 64x32
    const int wm = (wid >> 2) * 64;
    const int wn = (wid & 3) * 32;

    float d[4][4][4];
#pragma unroll
    for (int i = 0; i < 4; i++)
#pragma unroll
        for (int j = 0; j < 4; j++)
#pragma unroll
            for (int r = 0; r < 4; r++) d[i][j][r] = 0.0f;

    const int aRow = wm + (lane & 7) + ((lane >> 3) & 1) * 8;   // + f*16
    const int aC16 = ((lane >> 4) & 1) * 16;                     // + s*32
    const int bRow = wn + (lane & 7) + ((lane >> 4) & 1) * 8;   // + p*16
    const int bC16 = ((lane >> 3) & 1) * 16;                     // + s*32

    load_stage(0, ktBegin);
    if (ktBegin + 1 < ktEnd) load_stage(1, ktBegin + 1);

    for (int kt = ktBegin; kt < ktEnd; ++kt) {
        if (kt + 1 < ktEnd) asm volatile("cp.async.wait_group 1;" ::: "memory");
        else                asm volatile("cp.async.wait_group 0;" ::: "memory");
        __syncthreads();
        if (kt + 2 < ktEnd) load_stage((kt + 2 - ktBegin) % STAGES, kt + 2);

        uint32_t ab = sbase + ((kt - ktBegin) % STAGES) * STGB;
        uint32_t bb = ab + ASTG;

#pragma unroll
        for (int s = 0; s < 4; s++) {
            uint32_t a[4][4];
#pragma unroll
            for (int f = 0; f < 4; f++) {
                int row = aRow + f * 16;
                ldsm4(a[f][0], a[f][1], a[f][2], a[f][3],
                      ab + swz(row, s * 32 + aC16));
            }
            uint32_t b[2][4];
#pragma unroll
            for (int p = 0; p < 2; p++) {
                int row = bRow + p * 16;
                ldsm4(b[p][0], b[p][1], b[p][2], b[p][3],
                      bb + swz(row, s * 32 + bC16));
            }
#pragma unroll
            for (int mf = 0; mf < 4; mf++)
#pragma unroll
                for (int nf = 0; nf < 4; nf++) {
                    int p = nf >> 1, h = nf & 1;
                    mma16816(d[mf][nf], a[mf], b[p][h * 2], b[p][h * 2 + 1]);
                }
        }
    }

    const int q = lane >> 2;
    const int cp2 = (lane & 3) * 2;
#pragma unroll
    for (int mf = 0; mf < 4; mf++) {
#pragma unroll
        for (int nf = 0; nf < 4; nf++) {
            int row = m0 + wm + mf * 16 + q;
            int col = n0 + wn + nf * 8 + cp2;
#pragma unroll
            for (int half = 0; half < 2; half++) {
                size_t off = (size_t)(row + half * 8) * HH + col;
                *reinterpret_cast<float2*>(outP + off) =
                    make_float2(d[mf][nf][half * 2], d[mf][nf][half * 2 + 1]);
            }
        }
    }
}

extern "C" void kernel_launch(void* const* d_in, const int* in_sizes, int n_in,
                              void* d_out, int out_size) {
    const float* X = nullptr; const float* A = nullptr; const float* W = nullptr;
    for (int i = 0; i < n_in; i++) {
        if (in_sizes[i] == NN * NN * 8)      A = (const float*)d_in[i];
        else if (in_sizes[i] == NN * HH * 8) X = (const float*)d_in[i];
        else if (in_sizes[i] == HH * HH * 8) W = (const float*)d_in[i];
    }
    float* out = (float*)d_out;

    unsigned short *pAf, *pXf, *pWf, *pC1;
    float *pP1, *pP2;
    cudaGetSymbolAddress((void**)&pAf, g_Af);
    cudaGetSymbolAddress((void**)&pXf, g_Xf);
    cudaGetSymbolAddress((void**)&pWf, g_Wf);
    cudaGetSymbolAddress((void**)&pC1, g_C1);
    cudaGetSymbolAddress((void**)&pP1, g_P1);
    cudaGetSymbolAddress((void**)&pP2, g_P2);

    cudaFuncSetAttribute(gemm_kernel,
                         cudaFuncAttributeMaxDynamicSharedMemorySize, GSMEM);

    fwd_A_kernel<<<(int)(NA / 4 / 256), 256>>>(A, pAf, NA);
    fwd_T_kernel<<<(int)((NX + 255) / 256), 256>>>(X, pXf, NN, HH);
    fwd_T_kernel<<<(int)((NW + 255) / 256), 256>>>(W, pWf, HH, HH);

    // GEMM1: K = 2048 -> 32 chunks, split-K4 -> 8 chunks/CTA; grid 640 CTAs
    dim3 grid1(NN / BM, HH / BN, 4 * NJ);
    gemm_kernel<<<grid1, 256, GSMEM>>>(
        pAf, NN, NA, pXf, NN, NX, pP1, 8, 4);

    // reduce GEMM1 partials -> C1 fp16
    reduce4_kernel<<<(int)(NJ * NX / 4 / 256), 256>>>(pP1, pC1);

    // GEMM2: K = 256 -> 4 chunks, no split; grid 160 CTAs (single wave)
    dim3 grid2(NN / BM, HH / BN, NJ);
    gemm_kernel<<<grid2, 256, GSMEM>>>(
        pC1, HH, NX, pWf, HH, NW, pP2, 4, 1);

    inv_kernel<<<(int)((NX + 255) / 256), 256>>>(pP2, out, (int)NX);
}

// round 9
// speedup vs baseline: 3.9229x; 1.0034x over previous
#include <cuda_runtime.h>
#include <cuda_fp16.h>
#include <cstdint>

#define NN 2048
#define HH 256
#define NJ 5
#define RSQ2 0.70710678118654752440f

#define NA ((size_t)NN * NN)
#define NX ((size_t)NN * HH)
#define NW ((size_t)HH * HH)

// fp16 operands stored as ushort
__device__ unsigned short g_Af[NJ * NA];      // 41.9 MB  [j][node][k]
__device__ unsigned short g_Xf[NJ * NX];      //  5.2 MB  [j][hidden][node]
__device__ unsigned short g_Wf[NJ * NW];      //  0.65 MB [j][h_out][h_in]
__device__ unsigned short g_C1[NJ * NX];      //  5.2 MB  [j][node][h]
__device__ float          g_P1[3 * NJ * NX];  // 31.5 MB: GEMM1 split-K3 partials
__device__ float          g_P2[2 * NJ * NX];  // 21 MB:   GEMM2 split-K2 partials

__device__ __forceinline__ uint32_t smem_u32(const void* p) {
    uint32_t a;
    asm("{ .reg .u64 t; cvta.to.shared.u64 t, %1; cvt.u32.u64 %0, t; }"
        : "=r"(a) : "l"(p));
    return a;
}
__device__ __forceinline__ void cp16(uint32_t dst, const void* src) {
    asm volatile("cp.async.cg.shared.global [%0], [%1], 16;" :: "r"(dst), "l"(src));
}
__device__ __forceinline__ void ldsm4(uint32_t& r0, uint32_t& r1, uint32_t& r2,
                                      uint32_t& r3, uint32_t addr) {
    asm volatile("ldmatrix.sync.aligned.m8n8.x4.shared.b16 {%0,%1,%2,%3}, [%4];"
                 : "=r"(r0), "=r"(r1), "=r"(r2), "=r"(r3) : "r"(addr));
}
__device__ __forceinline__ void mma16816(float* d, const uint32_t* a,
                                         uint32_t b0, uint32_t b1) {
    asm volatile(
        "mma.sync.aligned.m16n8k16.row.col.f32.f16.f16.f32 "
        "{%0,%1,%2,%3}, {%4,%5,%6,%7}, {%8,%9}, {%0,%1,%2,%3};"
        : "+f"(d[0]), "+f"(d[1]), "+f"(d[2]), "+f"(d[3])
        : "r"(a[0]), "r"(a[1]), "r"(a[2]), "r"(a[3]), "r"(b0), "r"(b1));
}

__device__ __forceinline__ void cos5(float4 lo, float4 hi, float f[5]) {
    float s04 = lo.x + hi.x, d04 = lo.x - hi.x;
    float s26 = lo.z + hi.z;
    float s15 = lo.y + hi.y, d15 = lo.y - hi.y;
    float s37 = lo.w + hi.w, d37 = lo.w - hi.w;
    float t = RSQ2 * (d15 - d37);
    f[0] = (s04 + s26) + (s15 + s37);
    f[1] = d04 + t;
    f[2] = s04 - s26;
    f[3] = d04 - t;
    f[4] = (s04 + s26) - (s15 + s37);
}
__device__ __forceinline__ unsigned short h16(float f) {
    __half h = __float2half_rn(f);
    return *reinterpret_cast<unsigned short*>(&h);
}

// A: [n1][n2][8] -> Af [j][n1*NN+n2] fp16; 8 elements/thread, 16B stores
__global__ void fwd_A_kernel(const float* __restrict__ in,
                             unsigned short* __restrict__ o, size_t n) {
    size_t i0 = ((size_t)blockIdx.x * blockDim.x + threadIdx.x) * 8;
    if (i0 >= n) return;
    const float4* p = reinterpret_cast<const float4*>(in) + 2 * i0;
    unsigned short h[8][5];
#pragma unroll
    for (int e = 0; e < 8; e++) {
        float f[5]; cos5(p[2 * e], p[2 * e + 1], f);
#pragma unroll
        for (int j = 0; j < 5; j++) h[e][j] = h16(f[j]);
    }
#pragma unroll
    for (int j = 0; j < 5; j++) {
        *reinterpret_cast<uint4*>(o + j * n + i0) =
            make_uint4((uint32_t)h[0][j] | ((uint32_t)h[1][j] << 16),
                       (uint32_t)h[2][j] | ((uint32_t)h[3][j] << 16),
                       (uint32_t)h[4][j] | ((uint32_t)h[5][j] << 16),
                       (uint32_t)h[6][j] | ((uint32_t)h[7][j] << 16));
    }
}

// src [R][C][8] -> out [j][C][R] fp16 (transpose + cos)
__global__ void fwd_T_kernel(const float* __restrict__ in,
                             unsigned short* __restrict__ o,
                             int R, int C) {
    int i = blockIdx.x * blockDim.x + threadIdx.x;
    size_t n = (size_t)R * C;
    if (i >= (int)n) return;
    int c = i / R, r = i - c * R;
    const float4* p = reinterpret_cast<const float4*>(in) + 2 * ((size_t)r * C + c);
    float f[5]; cos5(p[0], p[1], f);
#pragma unroll
    for (int j = 0; j < 5; j++) o[j * n + i] = h16(f[j]);
}

// sum 3 split-K partials of GEMM1 -> fp16 C1
__global__ void reduce3_kernel(const float* __restrict__ P,
                               unsigned short* __restrict__ o) {
    size_t i0 = ((size_t)blockIdx.x * blockDim.x + threadIdx.x) * 4;
    size_t slice = i0 / NX;
    size_t r = i0 - slice * NX;
    const float* base = P + 3 * slice * NX + r;
    float4 s = *reinterpret_cast<const float4*>(base);
#pragma unroll
    for (int q = 1; q < 3; q++) {
        float4 v = *reinterpret_cast<const float4*>(base + q * NX);
        s.x += v.x; s.y += v.y; s.z += v.z; s.w += v.w;
    }
    *reinterpret_cast<uint2*>(o + i0) =
        make_uint2((uint32_t)h16(s.x) | ((uint32_t)h16(s.y) << 16),
                   (uint32_t)h16(s.z) | ((uint32_t)h16(s.w) << 16));
}

// inverse cos transform; folds GEMM2's 2-way split-K reduction
__global__ void inv_kernel(const float* __restrict__ P2,
                           float* __restrict__ out, int n) {
    int i = blockIdx.x * blockDim.x + threadIdx.x;
    if (i >= n) return;
    float g[5];
#pragma unroll
    for (int j = 0; j < 5; j++)
        g[j] = P2[(size_t)(2 * j) * NX + i] + P2[(size_t)(2 * j + 1) * NX + i];
    float d13 = 2.0f * RSQ2 * (g[1] - g[3]);
    float o0 = 0.125f * (g[0] + 2.0f * (g[1] + g[2] + g[3]) + g[4]);
    float o1 = 0.125f * ((g[0] - g[4]) + d13);
    float o2 = 0.125f * ((g[0] + g[4]) - 2.0f * g[2]);
    float o3 = 0.125f * ((g[0] - g[4]) - d13);
    float o4 = 0.125f * (g[0] - 2.0f * (g[1] - g[2] + g[3]) + g[4]);
    reinterpret_cast<float4*>(out)[(size_t)2 * i]     = make_float4(o0, o1, o2, o3);
    reinterpret_cast<float4*>(out)[(size_t)2 * i + 1] = make_float4(o4, o3, o2, o1);
}

// ---------------- fp16 mma.sync GEMM with split-K ---------------------------
// blockIdx.z = slice*splitCnt + part; CTA does chunks [part*nPer, min(kTot,..))
// into its own fp32 slab outP + z*NX.
#define BM 128
#define BN 128
#define ASTG (BM * 128)
#define BSTG (BN * 128)
#define STGB (ASTG + BSTG)
#define STAGES 3
#define GSMEM (STAGES * STGB)

__device__ __forceinline__ uint32_t swz(int row, int cbyte) {
    return (uint32_t)(row * 128 + (cbyte ^ ((row & 7) << 4)));
}

__global__ __launch_bounds__(256) void gemm_kernel(
    const unsigned short* __restrict__ A, int lda, size_t sA,
    const unsigned short* __restrict__ B, int ldb, size_t sB,
    float* __restrict__ outP, int nPer, int splitCnt, int kTot)
{
    extern __shared__ char smem[];
    const uint32_t sbase = smem_u32(smem);
    const int tid = threadIdx.x;
    const int wid = tid >> 5;
    const int lane = tid & 31;
    const int z = blockIdx.z;
    const int slice = z / splitCnt;
    const int part = z - slice * splitCnt;
    const int ktBegin = part * nPer;
    const int ktEnd = min(ktBegin + nPer, kTot);
    const int m0 = blockIdx.x * BM;
    const int n0 = blockIdx.y * BN;

    A += slice * sA;
    B += slice * sB;
    outP += (size_t)z * NX;

    const int lrow = tid >> 3;          // 0..31
    const int lc16 = (tid & 7) << 4;    // byte col 0..112
    auto load_stage = [&](int s, int ktl) {
        int kk = ktl * 64;
        uint32_t ab = sbase + s * STGB;
        uint32_t bb = ab + ASTG;
#pragma unroll
        for (int t = 0; t < 4; t++) {
            int row = lrow + t * 32;
            cp16(ab + swz(row, lc16), A + (size_t)(m0 + row) * lda + kk + (lc16 >> 1));
        }
#pragma unroll
        for (int t = 0; t < 4; t++) {
            int row = lrow + t * 32;
            cp16(bb + swz(row, lc16), B + (size_t)(n0 + row) * ldb + kk + (lc16 >> 1));
        }
        asm volatile("cp.async.commit_group;" ::: "memory");
    };

    // warp tiling: 2 (M) x 4 (N) warps, warp tile 64x32
    const int wm = (wid >> 2) * 64;
    const int wn = (wid & 3) * 32;

    float d[4][4][4];
#pragma unroll
    for (int i = 0; i < 4; i++)
#pragma unroll
        for (int j = 0; j < 4; j++)
#pragma unroll
            for (int r = 0; r < 4; r++) d[i][j][r] = 0.0f;

    const int aRow = wm + (lane & 7) + ((lane >> 3) & 1) * 8;   // + f*16
    const int aC16 = ((lane >> 4) & 1) * 16;                     // + s*32
    const int bRow = wn + (lane & 7) + ((lane >> 4) & 1) * 8;   // + p*16
    const int bC16 = ((lane >> 3) & 1) * 16;                     // + s*32

    load_stage(0, ktBegin);
    if (ktBegin + 1 < ktEnd) load_stage(1, ktBegin + 1);

    for (int kt = ktBegin; kt < ktEnd; ++kt) {
        if (kt + 1 < ktEnd) asm volatile("cp.async.wait_group 1;" ::: "memory");
        else                asm volatile("cp.async.wait_group 0;" ::: "memory");
        __syncthreads();
        if (kt + 2 < ktEnd) load_stage((kt + 2 - ktBegin) % STAGES, kt + 2);

        uint32_t ab = sbase + ((kt - ktBegin) % STAGES) * STGB;
        uint32_t bb = ab + ASTG;

#pragma unroll
        for (int s = 0; s < 4; s++) {
            uint32_t a[4][4];
#pragma unroll
            for (int f = 0; f < 4; f++) {
                int row = aRow + f * 16;
                ldsm4(a[f][0], a[f][1], a[f][2], a[f][3],
                      ab + swz(row, s * 32 + aC16));
            }
            uint32_t b[2][4];
#pragma unroll
            for (int p = 0; p < 2; p++) {
                int row = bRow + p * 16;
                ldsm4(b[p][0], b[p][1], b[p][2], b[p][3],
                      bb + swz(row, s * 32 + bC16));
            }
#pragma unroll
            for (int mf = 0; mf < 4; mf++)
#pragma unroll
                for (int nf = 0; nf < 4; nf++) {
                    int p = nf >> 1, h = nf & 1;
                    mma16816(d[mf][nf], a[mf], b[p][h * 2], b[p][h * 2 + 1]);
                }
        }
    }

    const int q = lane >> 2;
    const int cp2 = (lane & 3) * 2;
#pragma unroll
    for (int mf = 0; mf < 4; mf++) {
#pragma unroll
        for (int nf = 0; nf < 4; nf++) {
            int row = m0 + wm + mf * 16 + q;
            int col = n0 + wn + nf * 8 + cp2;
#pragma unroll
            for (int half = 0; half < 2; half++) {
                size_t off = (size_t)(row + half * 8) * HH + col;
                *reinterpret_cast<float2*>(outP + off) =
                    make_float2(d[mf][nf][half * 2], d[mf][nf][half * 2 + 1]);
            }
        }
    }
}

extern "C" void kernel_launch(void* const* d_in, const int* in_sizes, int n_in,
                              void* d_out, int out_size) {
    const float* X = nullptr; const float* A = nullptr; const float* W = nullptr;
    for (int i = 0; i < n_in; i++) {
        if (in_sizes[i] == NN * NN * 8)      A = (const float*)d_in[i];
        else if (in_sizes[i] == NN * HH * 8) X = (const float*)d_in[i];
        else if (in_sizes[i] == HH * HH * 8) W = (const float*)d_in[i];
    }
    float* out = (float*)d_out;

    unsigned short *pAf, *pXf, *pWf, *pC1;
    float *pP1, *pP2;
    cudaGetSymbolAddress((void**)&pAf, g_Af);
    cudaGetSymbolAddress((void**)&pXf, g_Xf);
    cudaGetSymbolAddress((void**)&pWf, g_Wf);
    cudaGetSymbolAddress((void**)&pC1, g_C1);
    cudaGetSymbolAddress((void**)&pP1, g_P1);
    cudaGetSymbolAddress((void**)&pP2, g_P2);

    cudaFuncSetAttribute(gemm_kernel,
                         cudaFuncAttributeMaxDynamicSharedMemorySize, GSMEM);

    fwd_A_kernel<<<(int)(NA / 8 / 256), 256>>>(A, pAf, NA);
    fwd_T_kernel<<<(int)((NX + 255) / 256), 256>>>(X, pXf, NN, HH);
    fwd_T_kernel<<<(int)((NW + 255) / 256), 256>>>(W, pWf, HH, HH);

    // GEMM1: K = 2048 -> 32 chunks, split-K3 (11/11/10); grid 480 CTAs
    dim3 grid1(NN / BM, HH / BN, 3 * NJ);
    gemm_kernel<<<grid1, 256, GSMEM>>>(
        pAf, NN, NA, pXf, NN, NX, pP1, 11, 3, 32);

    // reduce GEMM1 partials -> C1 fp16
    reduce3_kernel<<<(int)(NJ * NX / 4 / 256), 256>>>(pP1, pC1);

    // GEMM2: K = 256 -> 4 chunks, split-K2 (2/2); grid 320 CTAs
    dim3 grid2(NN / BM, HH / BN, 2 * NJ);
    gemm_kernel<<<grid2, 256, GSMEM>>>(
        pC1, HH, NX, pWf, HH, NW, pP2, 2, 2, 4);

    // inverse transform (folds GEMM2 partial reduction)
    inv_kernel<<<(int)((NX + 255) / 256), 256>>>(pP2, out, (int)NX);
}